// round 2
// baseline (speedup 1.0000x reference)
#include <cuda_runtime.h>
#include <math.h>

#define NN 50000
#define EE 800000
#define DD 128
#define WPAD 132   // padded k-stride for transposed W tiles (conflict-free float4 LDS)

// Scratch (device globals: no allocation allowed in kernel_launch)
__device__ __align__(16) float g_agg[(size_t)NN * DD];
__device__ __align__(16) float g_cnt[NN];
__device__ __align__(16) float g_h[(size_t)NN * DD];
__device__ int g_ei_is64;

// ---------------------------------------------------------------------------
// Detect edge_index dtype. Values are in [0, 50000), so for a little-endian
// int64 buffer every odd 32-bit word is 0. For an int32 buffer, 16 sampled
// odd words all being zero is impossible in practice (~(2e-5)^16).
// ---------------------------------------------------------------------------
__global__ void detect_kernel(const int* __restrict__ ei32) {
    int all0 = 1;
    #pragma unroll
    for (int i = 0; i < 16; i++)
        if (ei32[2 * i + 1] != 0) all0 = 0;
    g_ei_is64 = all0;
}

// ---------------------------------------------------------------------------
// Zero the aggregation buffers. zero_cnt!=0 also zeroes the count buffer.
// ---------------------------------------------------------------------------
__global__ void zero_kernel(int zero_cnt) {
    int i = blockIdx.x * blockDim.x + threadIdx.x;
    int stride = gridDim.x * blockDim.x;
    float4 z = make_float4(0.f, 0.f, 0.f, 0.f);
    float4* agg4 = reinterpret_cast<float4*>(g_agg);
    for (int k = i; k < NN * DD / 4; k += stride) agg4[k] = z;
    if (zero_cnt) {
        float4* cnt4 = reinterpret_cast<float4*>(g_cnt);
        for (int k = i; k < NN / 4; k += stride) cnt4[k] = z;
    }
}

// ---------------------------------------------------------------------------
// Edge scatter: one warp per edge. Lane l moves 4 consecutive floats.
// xin_is_gh selects layer-1 input (external x) vs layer-2 input (g_h).
// ---------------------------------------------------------------------------
__global__ void scatter_kernel(const float* __restrict__ x_ext,
                               const void* __restrict__ ei_raw,
                               int xin_is_gh, int do_cnt) {
    const float* __restrict__ x = xin_is_gh ? g_h : x_ext;
    int gw = (blockIdx.x * blockDim.x + threadIdx.x) >> 5;
    int lane = threadIdx.x & 31;
    if (gw >= EE) return;

    int src, dst;
    if (g_ei_is64) {
        const long long* ei = (const long long*)ei_raw;
        src = (int)ei[gw];
        dst = (int)ei[EE + gw];
    } else {
        const int* ei = (const int*)ei_raw;
        src = ei[gw];
        dst = ei[EE + gw];
    }

    float4 v = reinterpret_cast<const float4*>(x + (size_t)src * DD)[lane];
    float* a = g_agg + (size_t)dst * DD + lane * 4;
    atomicAdd(a + 0, v.x);
    atomicAdd(a + 1, v.y);
    atomicAdd(a + 2, v.z);
    atomicAdd(a + 3, v.w);
    if (do_cnt && lane == 0) atomicAdd(&g_cnt[dst], 1.0f);
}

// ---------------------------------------------------------------------------
// Fused SAGE layer epilogue:
//   mean = agg / max(cnt,1)
//   out  = mean @ W_l + b_l + x @ W_r
//   out  = relu(out / max(||out||_2, 1e-12))
//
// 256 threads/block. Thread = output column j = tid&127; half = tid>>7.
// Each iteration processes 8 rows (4 per half). W_l/W_r live transposed +
// padded in shared memory; inner loop is float4 LDS + FFMA, 8 acc chains.
// ---------------------------------------------------------------------------
__global__ void sage_layer(const float* __restrict__ xin_ext, int xin_is_gh,
                           const float* __restrict__ Wl,
                           const float* __restrict__ bl,
                           const float* __restrict__ Wr,
                           float* __restrict__ out_ext, int out_is_gh) {
    extern __shared__ float sh[];
    float* sWl = sh;                       // [128][WPAD], sWl[j*WPAD+k] = Wl[k*128+j]
    float* sWr = sWl + DD * WPAD;          // [128][WPAD]
    float* sm  = sWr + DD * WPAD;          // [8][128] mean rows
    float* sx  = sm + 8 * DD;              // [8][128] x rows
    float* red = sx + 8 * DD;              // [32] warp partials (8 warps x 4 rows)

    const float* __restrict__ xin = xin_is_gh ? g_h : xin_ext;
    float* __restrict__ outp = out_is_gh ? g_h : out_ext;

    int tid  = threadIdx.x;   // 0..255
    int j    = tid & 127;     // output column
    int half = tid >> 7;      // 0 or 1
    int warp = tid >> 5;      // 0..7
    int lane = tid & 31;

    // Load + transpose both weight matrices into shared
    for (int idx = tid; idx < DD * DD; idx += 256) {
        int k = idx >> 7;         // row of W (input feature)
        int jj = idx & 127;       // col of W (output feature)
        sWl[jj * WPAD + k] = Wl[idx];
        sWr[jj * WPAD + k] = Wr[idx];
    }
    float bj = bl[j];
    __syncthreads();

    for (int r0 = blockIdx.x * 8; r0 < NN; r0 += gridDim.x * 8) {
        // Stage this half's 4 rows (mean and x) into shared
        #pragma unroll
        for (int t = 0; t < 4; t++) {
            int trow = half * 4 + t;
            int r = r0 + trow;
            float av = 0.f, xv = 0.f;
            if (r < NN) {
                float inv = 1.0f / fmaxf(g_cnt[r], 1.0f);
                av = g_agg[(size_t)r * DD + j] * inv;
                xv = xin[(size_t)r * DD + j];
            }
            sm[trow * DD + j] = av;
            sx[trow * DD + j] = xv;
        }
        __syncthreads();

        float accl[4] = {0.f, 0.f, 0.f, 0.f};
        float accr[4] = {0.f, 0.f, 0.f, 0.f};
        const float* wlp = sWl + j * WPAD;
        const float* wrp = sWr + j * WPAD;

        #pragma unroll 4
        for (int k = 0; k < DD; k += 4) {
            float4 wl = *reinterpret_cast<const float4*>(wlp + k);
            float4 wr = *reinterpret_cast<const float4*>(wrp + k);
            #pragma unroll
            for (int t = 0; t < 4; t++) {
                int trow = half * 4 + t;
                float4 m  = *reinterpret_cast<const float4*>(sm + trow * DD + k);
                float4 xv = *reinterpret_cast<const float4*>(sx + trow * DD + k);
                accl[t] = fmaf(m.x,  wl.x, accl[t]);
                accl[t] = fmaf(m.y,  wl.y, accl[t]);
                accl[t] = fmaf(m.z,  wl.z, accl[t]);
                accl[t] = fmaf(m.w,  wl.w, accl[t]);
                accr[t] = fmaf(xv.x, wr.x, accr[t]);
                accr[t] = fmaf(xv.y, wr.y, accr[t]);
                accr[t] = fmaf(xv.z, wr.z, accr[t]);
                accr[t] = fmaf(xv.w, wr.w, accr[t]);
            }
        }

        float v[4];
        float ss[4];
        #pragma unroll
        for (int t = 0; t < 4; t++) {
            v[t] = accl[t] + accr[t] + bj;
            ss[t] = v[t] * v[t];
            #pragma unroll
            for (int o = 16; o > 0; o >>= 1)
                ss[t] += __shfl_xor_sync(0xffffffffu, ss[t], o);
        }
        if (lane == 0) {
            #pragma unroll
            for (int t = 0; t < 4; t++) red[warp * 4 + t] = ss[t];
        }
        __syncthreads();

        #pragma unroll
        for (int t = 0; t < 4; t++) {
            int trow = half * 4 + t;
            int wbase = half * 4;
            float s = red[(wbase + 0) * 4 + t] + red[(wbase + 1) * 4 + t]
                    + red[(wbase + 2) * 4 + t] + red[(wbase + 3) * 4 + t];
            float norm = fmaxf(sqrtf(s), 1e-12f);
            int r = r0 + trow;
            if (r < NN)
                outp[(size_t)r * DD + j] = fmaxf(v[t], 0.f) / norm;
        }
        __syncthreads();  // protect sm/sx/red before next iteration's writes
    }
}

// ---------------------------------------------------------------------------
// Launch sequence (all on the capture stream, no sync, no allocation)
// ---------------------------------------------------------------------------
extern "C" void kernel_launch(void* const* d_in, const int* in_sizes, int n_in,
                              void* d_out, int out_size) {
    const float* x   = (const float*)d_in[0];
    const void*  ei  = d_in[1];
    const float* W1l = (const float*)d_in[2];
    const float* b1l = (const float*)d_in[3];
    const float* W1r = (const float*)d_in[4];
    const float* W2l = (const float*)d_in[5];
    const float* b2l = (const float*)d_in[6];
    const float* W2r = (const float*)d_in[7];
    float* out = (float*)d_out;

    const int smem = (2 * DD * WPAD + 16 * DD + 32) * (int)sizeof(float);
    cudaFuncSetAttribute(sage_layer, cudaFuncAttributeMaxDynamicSharedMemorySize, smem);

    const int scatter_blocks = (EE * 32 + 255) / 256;

    // Probe edge_index dtype (int32 vs int64) once per launch sequence.
    detect_kernel<<<1, 1>>>((const int*)ei);

    // Layer 1
    zero_kernel<<<2048, 256>>>(1);
    scatter_kernel<<<scatter_blocks, 256>>>(x, ei, /*xin_is_gh=*/0, /*do_cnt=*/1);
    sage_layer<<<152, 256, smem>>>(x, /*xin_is_gh=*/0, W1l, b1l, W1r,
                                   out, /*out_is_gh=*/1);

    // Layer 2 (cnt is identical, only re-zero agg)
    zero_kernel<<<2048, 256>>>(0);
    scatter_kernel<<<scatter_blocks, 256>>>(x, ei, /*xin_is_gh=*/1, /*do_cnt=*/0);
    sage_layer<<<152, 256, smem>>>(x, /*xin_is_gh=*/1, W2l, b2l, W2r,
                                   out, /*out_is_gh=*/0);
}

// round 3
// speedup vs baseline: 1.1578x; 1.1578x over previous
#include <cuda_runtime.h>
#include <math.h>

#define NN 50000
#define EE 800000
#define DD 128
#define WPAD 132    // padded k-stride for transposed W tiles
#define RPT 8       // rows per thread in sage_layer
#define SAGE_THREADS 512
#define ROWS_PER_ITER (4 * RPT)   // 4 quarters x 8 rows = 32

// Scratch (device globals: no allocation allowed in kernel_launch)
__device__ __align__(16) float g_agg[(size_t)NN * DD];
__device__ __align__(16) float g_cnt[NN];
__device__ __align__(16) float g_h[(size_t)NN * DD];
__device__ int g_ei_is64;

// ---------------------------------------------------------------------------
// Detect edge_index dtype. Values are in [0, 50000), so for a little-endian
// int64 buffer every odd 32-bit word is 0. For an int32 buffer, 16 sampled
// odd words all being zero is impossible in practice.
// ---------------------------------------------------------------------------
__global__ void detect_kernel(const int* __restrict__ ei32) {
    int all0 = 1;
    #pragma unroll
    for (int i = 0; i < 16; i++)
        if (ei32[2 * i + 1] != 0) all0 = 0;
    g_ei_is64 = all0;
}

// ---------------------------------------------------------------------------
// Zero the aggregation buffers. zero_cnt!=0 also zeroes the count buffer.
// ---------------------------------------------------------------------------
__global__ void zero_kernel(int zero_cnt) {
    int i = blockIdx.x * blockDim.x + threadIdx.x;
    int stride = gridDim.x * blockDim.x;
    float4 z = make_float4(0.f, 0.f, 0.f, 0.f);
    float4* agg4 = reinterpret_cast<float4*>(g_agg);
    for (int k = i; k < NN * DD / 4; k += stride) agg4[k] = z;
    if (zero_cnt) {
        float4* cnt4 = reinterpret_cast<float4*>(g_cnt);
        for (int k = i; k < NN / 4; k += stride) cnt4[k] = z;
    }
}

// ---------------------------------------------------------------------------
// Edge scatter: one warp per edge. Lane l moves 4 consecutive floats.
// ---------------------------------------------------------------------------
__global__ void scatter_kernel(const float* __restrict__ x_ext,
                               const void* __restrict__ ei_raw,
                               int xin_is_gh, int do_cnt) {
    const float* __restrict__ x = xin_is_gh ? g_h : x_ext;
    int gw = (blockIdx.x * blockDim.x + threadIdx.x) >> 5;
    int lane = threadIdx.x & 31;
    if (gw >= EE) return;

    int src, dst;
    if (g_ei_is64) {
        const long long* ei = (const long long*)ei_raw;
        src = (int)ei[gw];
        dst = (int)ei[EE + gw];
    } else {
        const int* ei = (const int*)ei_raw;
        src = ei[gw];
        dst = ei[EE + gw];
    }

    float4 v = reinterpret_cast<const float4*>(x + (size_t)src * DD)[lane];
    float* a = g_agg + (size_t)dst * DD + lane * 4;
    atomicAdd(a + 0, v.x);
    atomicAdd(a + 1, v.y);
    atomicAdd(a + 2, v.z);
    atomicAdd(a + 3, v.w);
    if (do_cnt && lane == 0) atomicAdd(&g_cnt[dst], 1.0f);
}

// ---------------------------------------------------------------------------
// Fused SAGE layer epilogue:
//   mean = agg / max(cnt,1);  out = mean @ W_l + b_l + x @ W_r
//   out  = relu(out / max(||out||_2, 1e-12))
//
// 512 threads. Thread = column j = tid&127, quarter q = tid>>7 (0..3).
// Each iteration processes 32 rows (8 per quarter, RPT per thread).
// Weights transposed+padded in smem; 16 independent FFMA chains per thread.
// ---------------------------------------------------------------------------
__global__ void __launch_bounds__(SAGE_THREADS, 1)
sage_layer(const float* __restrict__ xin_ext, int xin_is_gh,
           const float* __restrict__ Wl,
           const float* __restrict__ bl,
           const float* __restrict__ Wr,
           float* __restrict__ out_ext, int out_is_gh) {
    extern __shared__ float sh[];
    float* sWl = sh;                         // [128][WPAD]
    float* sWr = sWl + DD * WPAD;            // [128][WPAD]
    float* sm  = sWr + DD * WPAD;            // [32][128] mean rows
    float* sx  = sm + ROWS_PER_ITER * DD;    // [32][128] x rows
    float* red = sx + ROWS_PER_ITER * DD;    // [16 warps][RPT]

    const float* __restrict__ xin = xin_is_gh ? g_h : xin_ext;
    float* __restrict__ outp = out_is_gh ? g_h : out_ext;

    int tid  = threadIdx.x;    // 0..511
    int j    = tid & 127;      // output column
    int q    = tid >> 7;       // quarter 0..3
    int warp = tid >> 5;       // 0..15
    int lane = tid & 31;

    // Load + transpose both weight matrices into shared
    for (int idx = tid; idx < DD * DD; idx += SAGE_THREADS) {
        int k = idx >> 7;
        int jj = idx & 127;
        sWl[jj * WPAD + k] = Wl[idx];
        sWr[jj * WPAD + k] = Wr[idx];
    }
    float bj = bl[j];
    __syncthreads();

    for (int r0 = blockIdx.x * ROWS_PER_ITER; r0 < NN;
         r0 += gridDim.x * ROWS_PER_ITER) {
        // Stage this quarter's RPT rows (mean and x) into shared
        #pragma unroll
        for (int t = 0; t < RPT; t++) {
            int trow = q * RPT + t;
            int r = r0 + trow;
            float av = 0.f, xv = 0.f;
            if (r < NN) {
                float inv = 1.0f / fmaxf(g_cnt[r], 1.0f);
                av = g_agg[(size_t)r * DD + j] * inv;
                xv = xin[(size_t)r * DD + j];
            }
            sm[trow * DD + j] = av;
            sx[trow * DD + j] = xv;
        }
        __syncthreads();

        float accl[RPT], accr[RPT];
        #pragma unroll
        for (int t = 0; t < RPT; t++) { accl[t] = 0.f; accr[t] = 0.f; }

        const float* wlp = sWl + j * WPAD;
        const float* wrp = sWr + j * WPAD;
        const float* smq = sm + q * RPT * DD;
        const float* sxq = sx + q * RPT * DD;

        #pragma unroll 2
        for (int k = 0; k < DD; k += 4) {
            float4 wl = *reinterpret_cast<const float4*>(wlp + k);
            float4 wr = *reinterpret_cast<const float4*>(wrp + k);
            #pragma unroll
            for (int t = 0; t < RPT; t++) {
                float4 m  = *reinterpret_cast<const float4*>(smq + t * DD + k);
                float4 xv = *reinterpret_cast<const float4*>(sxq + t * DD + k);
                accl[t] = fmaf(m.x,  wl.x, accl[t]);
                accl[t] = fmaf(m.y,  wl.y, accl[t]);
                accl[t] = fmaf(m.z,  wl.z, accl[t]);
                accl[t] = fmaf(m.w,  wl.w, accl[t]);
                accr[t] = fmaf(xv.x, wr.x, accr[t]);
                accr[t] = fmaf(xv.y, wr.y, accr[t]);
                accr[t] = fmaf(xv.z, wr.z, accr[t]);
                accr[t] = fmaf(xv.w, wr.w, accr[t]);
            }
        }

        float v[RPT];
        #pragma unroll
        for (int t = 0; t < RPT; t++) {
            v[t] = accl[t] + accr[t] + bj;
            float ss = v[t] * v[t];
            #pragma unroll
            for (int o = 16; o > 0; o >>= 1)
                ss += __shfl_xor_sync(0xffffffffu, ss, o);
            if (lane == 0) red[warp * RPT + t] = ss;
        }
        __syncthreads();

        #pragma unroll
        for (int t = 0; t < RPT; t++) {
            int trow = q * RPT + t;
            int wbase = q * 4;   // 4 warps per quarter
            float s = red[(wbase + 0) * RPT + t] + red[(wbase + 1) * RPT + t]
                    + red[(wbase + 2) * RPT + t] + red[(wbase + 3) * RPT + t];
            float norm = fmaxf(sqrtf(s), 1e-12f);
            int r = r0 + trow;
            if (r < NN)
                outp[(size_t)r * DD + j] = fmaxf(v[t], 0.f) / norm;
        }
        __syncthreads();  // protect sm/sx/red before next iteration's writes
    }
}

// ---------------------------------------------------------------------------
// Launch sequence (all on the capture stream, no sync, no allocation)
// ---------------------------------------------------------------------------
extern "C" void kernel_launch(void* const* d_in, const int* in_sizes, int n_in,
                              void* d_out, int out_size) {
    const float* x   = (const float*)d_in[0];
    const void*  ei  = d_in[1];
    const float* W1l = (const float*)d_in[2];
    const float* b1l = (const float*)d_in[3];
    const float* W1r = (const float*)d_in[4];
    const float* W2l = (const float*)d_in[5];
    const float* b2l = (const float*)d_in[6];
    const float* W2r = (const float*)d_in[7];
    float* out = (float*)d_out;

    const int smem = (2 * DD * WPAD + 2 * ROWS_PER_ITER * DD + 16 * RPT)
                     * (int)sizeof(float);
    cudaFuncSetAttribute(sage_layer, cudaFuncAttributeMaxDynamicSharedMemorySize, smem);

    const int scatter_blocks = (EE * 32 + 255) / 256;

    // Probe edge_index dtype (int32 vs int64) once per launch sequence.
    detect_kernel<<<1, 1>>>((const int*)ei);

    // Layer 1
    zero_kernel<<<2048, 256>>>(1);
    scatter_kernel<<<scatter_blocks, 256>>>(x, ei, /*xin_is_gh=*/0, /*do_cnt=*/1);
    sage_layer<<<152, SAGE_THREADS, smem>>>(x, /*xin_is_gh=*/0, W1l, b1l, W1r,
                                            out, /*out_is_gh=*/1);

    // Layer 2 (cnt is identical, only re-zero agg)
    zero_kernel<<<2048, 256>>>(0);
    scatter_kernel<<<scatter_blocks, 256>>>(x, ei, /*xin_is_gh=*/1, /*do_cnt=*/0);
    sage_layer<<<152, SAGE_THREADS, smem>>>(x, /*xin_is_gh=*/1, W2l, b2l, W2r,
                                            out, /*out_is_gh=*/0);
}

// round 4
// speedup vs baseline: 2.4644x; 2.1285x over previous
#include <cuda_runtime.h>
#include <math.h>

#define NN 50000
#define EE 800000
#define DD 128
#define SAGE_THREADS 512          // 16 warps
#define ROWS_PER_ITER 64          // 16 warps x 4 rows

// Scratch (device globals: no allocation allowed in kernel_launch)
__device__ __align__(16) float g_agg[(size_t)NN * DD];
__device__ __align__(16) float g_cnt[NN];
__device__ __align__(16) float g_h[(size_t)NN * DD];
__device__ int g_ei_is64;

// ---------------------------------------------------------------------------
// Detect edge_index dtype. Values are in [0, 50000), so for a little-endian
// int64 buffer every odd 32-bit word is 0. For an int32 buffer, 16 sampled
// odd words all being zero is impossible in practice.
// ---------------------------------------------------------------------------
__global__ void detect_kernel(const int* __restrict__ ei32) {
    int all0 = 1;
    #pragma unroll
    for (int i = 0; i < 16; i++)
        if (ei32[2 * i + 1] != 0) all0 = 0;
    g_ei_is64 = all0;
}

// ---------------------------------------------------------------------------
// Zero the aggregation buffers. zero_cnt!=0 also zeroes the count buffer.
// ---------------------------------------------------------------------------
__global__ void zero_kernel(int zero_cnt) {
    int i = blockIdx.x * blockDim.x + threadIdx.x;
    int stride = gridDim.x * blockDim.x;
    float4 z = make_float4(0.f, 0.f, 0.f, 0.f);
    float4* agg4 = reinterpret_cast<float4*>(g_agg);
    for (int k = i; k < NN * DD / 4; k += stride) agg4[k] = z;
    if (zero_cnt) {
        float4* cnt4 = reinterpret_cast<float4*>(g_cnt);
        for (int k = i; k < NN / 4; k += stride) cnt4[k] = z;
    }
}

// ---------------------------------------------------------------------------
// Edge scatter: one warp per edge. Lane l handles 4 consecutive floats via
// a single vectorized red.global.add.v4.f32 (PTX ISA 8.1, sm_90+).
// ---------------------------------------------------------------------------
__global__ void scatter_kernel(const float* __restrict__ x_ext,
                               const void* __restrict__ ei_raw,
                               int xin_is_gh, int do_cnt) {
    const float* __restrict__ x = xin_is_gh ? g_h : x_ext;
    int gw = (blockIdx.x * blockDim.x + threadIdx.x) >> 5;
    int lane = threadIdx.x & 31;
    if (gw >= EE) return;

    int src, dst;
    if (g_ei_is64) {
        const long long* ei = (const long long*)ei_raw;
        src = (int)ei[gw];
        dst = (int)ei[EE + gw];
    } else {
        const int* ei = (const int*)ei_raw;
        src = ei[gw];
        dst = ei[EE + gw];
    }

    float4 v = reinterpret_cast<const float4*>(x + (size_t)src * DD)[lane];
    float* a = g_agg + (size_t)dst * DD + lane * 4;
    asm volatile("red.global.add.v4.f32 [%0], {%1, %2, %3, %4};"
                 :: "l"(a), "f"(v.x), "f"(v.y), "f"(v.z), "f"(v.w)
                 : "memory");
    if (do_cnt && lane == 0) atomicAdd(&g_cnt[dst], 1.0f);
}

// ---------------------------------------------------------------------------
// Fused SAGE layer:
//   mean = agg / max(cnt,1);  out = mean @ W_l + b_l + x @ W_r
//   out  = relu(out / max(||out||_2, 1e-12))
//
// 512 threads = 16 warps. Each iteration covers 64 rows. Warp g owns rows
// 4g..4g+3; lane c owns output columns 4c..4c+3 (float4). Weights are staged
// k-major in smem (contiguous 512B per warp LDS -> conflict-free). Row tiles
// are warp-private in smem (broadcast LDS). No block barriers in main loop;
// row norm is a warp-local butterfly reduction.
// ---------------------------------------------------------------------------
__global__ void __launch_bounds__(SAGE_THREADS, 1)
sage_layer(const float* __restrict__ xin_ext, int xin_is_gh,
           const float* __restrict__ Wl,
           const float* __restrict__ bl,
           const float* __restrict__ Wr,
           float* __restrict__ out_ext, int out_is_gh) {
    extern __shared__ float sh[];
    float* sWl = sh;                  // [128][128] k-major
    float* sWr = sWl + DD * DD;       // [128][128]
    float* srows = sWr + DD * DD;     // 16 warps x [8][128]: 4 mean rows, 4 x rows

    const float* __restrict__ xin = xin_is_gh ? g_h : xin_ext;
    float* __restrict__ outp = out_is_gh ? g_h : out_ext;

    int tid  = threadIdx.x;
    int warp = tid >> 5;
    int lane = tid & 31;

    // Stage weights (unpermuted, k-major)
    for (int idx = tid; idx < DD * DD; idx += SAGE_THREADS) {
        sWl[idx] = Wl[idx];
        sWr[idx] = Wr[idx];
    }
    float4 b4 = reinterpret_cast<const float4*>(bl)[lane];
    __syncthreads();

    float* mrow = srows + warp * 8 * DD;   // [4][128]
    float* xrow = mrow + 4 * DD;           // [4][128]

    for (int r0 = blockIdx.x * ROWS_PER_ITER; r0 < NN;
         r0 += gridDim.x * ROWS_PER_ITER) {
        int rbase = r0 + warp * 4;

        // Stage this warp's 4 rows (mean + x), float4 per lane (coalesced)
        #pragma unroll
        for (int t = 0; t < 4; t++) {
            int r = rbase + t;
            float4 a = make_float4(0.f, 0.f, 0.f, 0.f);
            float4 xv = a;
            if (r < NN) {
                float inv = 1.0f / fmaxf(g_cnt[r], 1.0f);
                a = reinterpret_cast<const float4*>(g_agg + (size_t)r * DD)[lane];
                a.x *= inv; a.y *= inv; a.z *= inv; a.w *= inv;
                xv = reinterpret_cast<const float4*>(xin + (size_t)r * DD)[lane];
            }
            reinterpret_cast<float4*>(mrow + t * DD)[lane] = a;
            reinterpret_cast<float4*>(xrow + t * DD)[lane] = xv;
        }
        __syncwarp();

        float4 acc[4];
        #pragma unroll
        for (int t = 0; t < 4; t++) acc[t] = make_float4(0.f, 0.f, 0.f, 0.f);

        #pragma unroll 2
        for (int k = 0; k < DD; k += 4) {
            float4 wl0 = *reinterpret_cast<const float4*>(sWl + (k + 0) * DD + 4 * lane);
            float4 wl1 = *reinterpret_cast<const float4*>(sWl + (k + 1) * DD + 4 * lane);
            float4 wl2 = *reinterpret_cast<const float4*>(sWl + (k + 2) * DD + 4 * lane);
            float4 wl3 = *reinterpret_cast<const float4*>(sWl + (k + 3) * DD + 4 * lane);
            float4 wr0 = *reinterpret_cast<const float4*>(sWr + (k + 0) * DD + 4 * lane);
            float4 wr1 = *reinterpret_cast<const float4*>(sWr + (k + 1) * DD + 4 * lane);
            float4 wr2 = *reinterpret_cast<const float4*>(sWr + (k + 2) * DD + 4 * lane);
            float4 wr3 = *reinterpret_cast<const float4*>(sWr + (k + 3) * DD + 4 * lane);
            #pragma unroll
            for (int t = 0; t < 4; t++) {
                float4 m = *reinterpret_cast<const float4*>(mrow + t * DD + k);
                float4 xv = *reinterpret_cast<const float4*>(xrow + t * DD + k);
                acc[t].x = fmaf(m.x, wl0.x, acc[t].x);
                acc[t].y = fmaf(m.x, wl0.y, acc[t].y);
                acc[t].z = fmaf(m.x, wl0.z, acc[t].z);
                acc[t].w = fmaf(m.x, wl0.w, acc[t].w);
                acc[t].x = fmaf(m.y, wl1.x, acc[t].x);
                acc[t].y = fmaf(m.y, wl1.y, acc[t].y);
                acc[t].z = fmaf(m.y, wl1.z, acc[t].z);
                acc[t].w = fmaf(m.y, wl1.w, acc[t].w);
                acc[t].x = fmaf(m.z, wl2.x, acc[t].x);
                acc[t].y = fmaf(m.z, wl2.y, acc[t].y);
                acc[t].z = fmaf(m.z, wl2.z, acc[t].z);
                acc[t].w = fmaf(m.z, wl2.w, acc[t].w);
                acc[t].x = fmaf(m.w, wl3.x, acc[t].x);
                acc[t].y = fmaf(m.w, wl3.y, acc[t].y);
                acc[t].z = fmaf(m.w, wl3.z, acc[t].z);
                acc[t].w = fmaf(m.w, wl3.w, acc[t].w);
                acc[t].x = fmaf(xv.x, wr0.x, acc[t].x);
                acc[t].y = fmaf(xv.x, wr0.y, acc[t].y);
                acc[t].z = fmaf(xv.x, wr0.z, acc[t].z);
                acc[t].w = fmaf(xv.x, wr0.w, acc[t].w);
                acc[t].x = fmaf(xv.y, wr1.x, acc[t].x);
                acc[t].y = fmaf(xv.y, wr1.y, acc[t].y);
                acc[t].z = fmaf(xv.y, wr1.z, acc[t].z);
                acc[t].w = fmaf(xv.y, wr1.w, acc[t].w);
                acc[t].x = fmaf(xv.z, wr2.x, acc[t].x);
                acc[t].y = fmaf(xv.z, wr2.y, acc[t].y);
                acc[t].z = fmaf(xv.z, wr2.z, acc[t].z);
                acc[t].w = fmaf(xv.z, wr2.w, acc[t].w);
                acc[t].x = fmaf(xv.w, wr3.x, acc[t].x);
                acc[t].y = fmaf(xv.w, wr3.y, acc[t].y);
                acc[t].z = fmaf(xv.w, wr3.z, acc[t].z);
                acc[t].w = fmaf(xv.w, wr3.w, acc[t].w);
            }
        }

        // Epilogue: bias, warp-local L2 norm per row, relu, store
        #pragma unroll
        for (int t = 0; t < 4; t++) {
            float4 v = acc[t];
            v.x += b4.x; v.y += b4.y; v.z += b4.z; v.w += b4.w;
            float ss = v.x * v.x + v.y * v.y + v.z * v.z + v.w * v.w;
            #pragma unroll
            for (int o = 16; o > 0; o >>= 1)
                ss += __shfl_xor_sync(0xffffffffu, ss, o);
            float inv_norm = 1.0f / fmaxf(sqrtf(ss), 1e-12f);
            int r = rbase + t;
            if (r < NN) {
                float4 o4;
                o4.x = fmaxf(v.x, 0.f) * inv_norm;
                o4.y = fmaxf(v.y, 0.f) * inv_norm;
                o4.z = fmaxf(v.z, 0.f) * inv_norm;
                o4.w = fmaxf(v.w, 0.f) * inv_norm;
                reinterpret_cast<float4*>(outp + (size_t)r * DD)[lane] = o4;
            }
        }
        __syncwarp();   // rows buffer reused next iteration (warp-private)
    }
}

// ---------------------------------------------------------------------------
// Launch sequence (all on the capture stream, no sync, no allocation)
// ---------------------------------------------------------------------------
extern "C" void kernel_launch(void* const* d_in, const int* in_sizes, int n_in,
                              void* d_out, int out_size) {
    const float* x   = (const float*)d_in[0];
    const void*  ei  = d_in[1];
    const float* W1l = (const float*)d_in[2];
    const float* b1l = (const float*)d_in[3];
    const float* W1r = (const float*)d_in[4];
    const float* W2l = (const float*)d_in[5];
    const float* b2l = (const float*)d_in[6];
    const float* W2r = (const float*)d_in[7];
    float* out = (float*)d_out;

    const int smem = (2 * DD * DD + 16 * 8 * DD) * (int)sizeof(float);  // 192 KB
    cudaFuncSetAttribute(sage_layer, cudaFuncAttributeMaxDynamicSharedMemorySize, smem);

    const int scatter_blocks = (EE * 32 + 255) / 256;

    // Probe edge_index dtype (int32 vs int64) once per launch sequence.
    detect_kernel<<<1, 1>>>((const int*)ei);

    // Layer 1
    zero_kernel<<<2048, 256>>>(1);
    scatter_kernel<<<scatter_blocks, 256>>>(x, ei, /*xin_is_gh=*/0, /*do_cnt=*/1);
    sage_layer<<<152, SAGE_THREADS, smem>>>(x, /*xin_is_gh=*/0, W1l, b1l, W1r,
                                            out, /*out_is_gh=*/1);

    // Layer 2 (cnt is identical, only re-zero agg)
    zero_kernel<<<2048, 256>>>(0);
    scatter_kernel<<<scatter_blocks, 256>>>(x, ei, /*xin_is_gh=*/1, /*do_cnt=*/0);
    sage_layer<<<152, SAGE_THREADS, smem>>>(x, /*xin_is_gh=*/1, W2l, b2l, W2r,
                                            out, /*out_is_gh=*/0);
}

// round 5
// speedup vs baseline: 2.4701x; 1.0023x over previous
#include <cuda_runtime.h>
#include <math.h>

#define NN 50000
#define EE 800000
#define DD 128
#define SAGE_THREADS 512          // 16 warps
#define ROWS_PER_ITER 64          // 16 warps x 4 rows

// Scratch (device globals: no allocation allowed in kernel_launch)
__device__ __align__(16) float g_agg[(size_t)NN * DD];
__device__ __align__(16) float g_cnt[NN];
__device__ __align__(16) float g_h[(size_t)NN * DD];
__device__ int g_ei_is64;

// ---------------------------------------------------------------------------
// Detect edge_index dtype. Values are in [0, 50000), so for a little-endian
// int64 buffer every odd 32-bit word is 0. For an int32 buffer, 16 sampled
// odd words all being zero is impossible in practice.
// ---------------------------------------------------------------------------
__global__ void detect_kernel(const int* __restrict__ ei32) {
    int all0 = 1;
    #pragma unroll
    for (int i = 0; i < 16; i++)
        if (ei32[2 * i + 1] != 0) all0 = 0;
    g_ei_is64 = all0;
}

// ---------------------------------------------------------------------------
// Zero the aggregation buffers. zero_cnt!=0 also zeroes the count buffer.
// ---------------------------------------------------------------------------
__global__ void zero_kernel(int zero_cnt) {
    int i = blockIdx.x * blockDim.x + threadIdx.x;
    int stride = gridDim.x * blockDim.x;
    float4 z = make_float4(0.f, 0.f, 0.f, 0.f);
    float4* agg4 = reinterpret_cast<float4*>(g_agg);
    for (int k = i; k < NN * DD / 4; k += stride) agg4[k] = z;
    if (zero_cnt) {
        float4* cnt4 = reinterpret_cast<float4*>(g_cnt);
        for (int k = i; k < NN / 4; k += stride) cnt4[k] = z;
    }
}

// ---------------------------------------------------------------------------
// Edge scatter: one warp per edge. Lane l handles 4 consecutive floats via
// a single vectorized red.global.add.v4.f32 (PTX ISA 8.1, sm_90+).
// ---------------------------------------------------------------------------
__global__ void scatter_kernel(const float* __restrict__ x_ext,
                               const void* __restrict__ ei_raw,
                               int xin_is_gh, int do_cnt) {
    const float* __restrict__ x = xin_is_gh ? g_h : x_ext;
    int gw = (blockIdx.x * blockDim.x + threadIdx.x) >> 5;
    int lane = threadIdx.x & 31;
    if (gw >= EE) return;

    int src, dst;
    if (g_ei_is64) {
        const long long* ei = (const long long*)ei_raw;
        src = (int)ei[gw];
        dst = (int)ei[EE + gw];
    } else {
        const int* ei = (const int*)ei_raw;
        src = ei[gw];
        dst = ei[EE + gw];
    }

    float4 v = reinterpret_cast<const float4*>(x + (size_t)src * DD)[lane];
    float* a = g_agg + (size_t)dst * DD + lane * 4;
    asm volatile("red.global.add.v4.f32 [%0], {%1, %2, %3, %4};"
                 :: "l"(a), "f"(v.x), "f"(v.y), "f"(v.z), "f"(v.w)
                 : "memory");
    if (do_cnt && lane == 0) atomicAdd(&g_cnt[dst], 1.0f);
}

// ---------------------------------------------------------------------------
// Fused SAGE layer:
//   mean = agg / max(cnt,1);  out = mean @ W_l + b_l + x @ W_r
//   out  = relu(out / max(||out||_2, 1e-12))
//
// 512 threads = 16 warps. Each iteration covers 64 rows. Warp g owns rows
// 4g..4g+3; lane c owns output columns 4c..4c+3 (float4). Weights are staged
// k-major in smem (contiguous 512B per warp LDS -> conflict-free). Row tiles
// are warp-private in smem (broadcast LDS). No block barriers in main loop;
// row norm is a warp-local butterfly reduction.
// ---------------------------------------------------------------------------
__global__ void __launch_bounds__(SAGE_THREADS, 1)
sage_layer(const float* __restrict__ xin_ext, int xin_is_gh,
           const float* __restrict__ Wl,
           const float* __restrict__ bl,
           const float* __restrict__ Wr,
           float* __restrict__ out_ext, int out_is_gh) {
    extern __shared__ float sh[];
    float* sWl = sh;                  // [128][128] k-major
    float* sWr = sWl + DD * DD;       // [128][128]
    float* srows = sWr + DD * DD;     // 16 warps x [8][128]: 4 mean rows, 4 x rows

    const float* __restrict__ xin = xin_is_gh ? g_h : xin_ext;
    float* __restrict__ outp = out_is_gh ? g_h : out_ext;

    int tid  = threadIdx.x;
    int warp = tid >> 5;
    int lane = tid & 31;

    // Stage weights (unpermuted, k-major)
    for (int idx = tid; idx < DD * DD; idx += SAGE_THREADS) {
        sWl[idx] = Wl[idx];
        sWr[idx] = Wr[idx];
    }
    float4 b4 = reinterpret_cast<const float4*>(bl)[lane];
    __syncthreads();

    float* mrow = srows + warp * 8 * DD;   // [4][128]
    float* xrow = mrow + 4 * DD;           // [4][128]

    for (int r0 = blockIdx.x * ROWS_PER_ITER; r0 < NN;
         r0 += gridDim.x * ROWS_PER_ITER) {
        int rbase = r0 + warp * 4;

        // Stage this warp's 4 rows (mean + x), float4 per lane (coalesced)
        #pragma unroll
        for (int t = 0; t < 4; t++) {
            int r = rbase + t;
            float4 a = make_float4(0.f, 0.f, 0.f, 0.f);
            float4 xv = a;
            if (r < NN) {
                float inv = 1.0f / fmaxf(g_cnt[r], 1.0f);
                a = reinterpret_cast<const float4*>(g_agg + (size_t)r * DD)[lane];
                a.x *= inv; a.y *= inv; a.z *= inv; a.w *= inv;
                xv = reinterpret_cast<const float4*>(xin + (size_t)r * DD)[lane];
            }
            reinterpret_cast<float4*>(mrow + t * DD)[lane] = a;
            reinterpret_cast<float4*>(xrow + t * DD)[lane] = xv;
        }
        __syncwarp();

        float4 acc[4];
        #pragma unroll
        for (int t = 0; t < 4; t++) acc[t] = make_float4(0.f, 0.f, 0.f, 0.f);

        #pragma unroll 2
        for (int k = 0; k < DD; k += 4) {
            float4 wl0 = *reinterpret_cast<const float4*>(sWl + (k + 0) * DD + 4 * lane);
            float4 wl1 = *reinterpret_cast<const float4*>(sWl + (k + 1) * DD + 4 * lane);
            float4 wl2 = *reinterpret_cast<const float4*>(sWl + (k + 2) * DD + 4 * lane);
            float4 wl3 = *reinterpret_cast<const float4*>(sWl + (k + 3) * DD + 4 * lane);
            float4 wr0 = *reinterpret_cast<const float4*>(sWr + (k + 0) * DD + 4 * lane);
            float4 wr1 = *reinterpret_cast<const float4*>(sWr + (k + 1) * DD + 4 * lane);
            float4 wr2 = *reinterpret_cast<const float4*>(sWr + (k + 2) * DD + 4 * lane);
            float4 wr3 = *reinterpret_cast<const float4*>(sWr + (k + 3) * DD + 4 * lane);
            #pragma unroll
            for (int t = 0; t < 4; t++) {
                float4 m = *reinterpret_cast<const float4*>(mrow + t * DD + k);
                float4 xv = *reinterpret_cast<const float4*>(xrow + t * DD + k);
                acc[t].x = fmaf(m.x, wl0.x, acc[t].x);
                acc[t].y = fmaf(m.x, wl0.y, acc[t].y);
                acc[t].z = fmaf(m.x, wl0.z, acc[t].z);
                acc[t].w = fmaf(m.x, wl0.w, acc[t].w);
                acc[t].x = fmaf(m.y, wl1.x, acc[t].x);
                acc[t].y = fmaf(m.y, wl1.y, acc[t].y);
                acc[t].z = fmaf(m.y, wl1.z, acc[t].z);
                acc[t].w = fmaf(m.y, wl1.w, acc[t].w);
                acc[t].x = fmaf(m.z, wl2.x, acc[t].x);
                acc[t].y = fmaf(m.z, wl2.y, acc[t].y);
                acc[t].z = fmaf(m.z, wl2.z, acc[t].z);
                acc[t].w = fmaf(m.z, wl2.w, acc[t].w);
                acc[t].x = fmaf(m.w, wl3.x, acc[t].x);
                acc[t].y = fmaf(m.w, wl3.y, acc[t].y);
                acc[t].z = fmaf(m.w, wl3.z, acc[t].z);
                acc[t].w = fmaf(m.w, wl3.w, acc[t].w);
                acc[t].x = fmaf(xv.x, wr0.x, acc[t].x);
                acc[t].y = fmaf(xv.x, wr0.y, acc[t].y);
                acc[t].z = fmaf(xv.x, wr0.z, acc[t].z);
                acc[t].w = fmaf(xv.x, wr0.w, acc[t].w);
                acc[t].x = fmaf(xv.y, wr1.x, acc[t].x);
                acc[t].y = fmaf(xv.y, wr1.y, acc[t].y);
                acc[t].z = fmaf(xv.y, wr1.z, acc[t].z);
                acc[t].w = fmaf(xv.y, wr1.w, acc[t].w);
                acc[t].x = fmaf(xv.z, wr2.x, acc[t].x);
                acc[t].y = fmaf(xv.z, wr2.y, acc[t].y);
                acc[t].z = fmaf(xv.z, wr2.z, acc[t].z);
                acc[t].w = fmaf(xv.z, wr2.w, acc[t].w);
                acc[t].x = fmaf(xv.w, wr3.x, acc[t].x);
                acc[t].y = fmaf(xv.w, wr3.y, acc[t].y);
                acc[t].z = fmaf(xv.w, wr3.z, acc[t].z);
                acc[t].w = fmaf(xv.w, wr3.w, acc[t].w);
            }
        }

        // Epilogue: bias, warp-local L2 norm per row, relu, store
        #pragma unroll
        for (int t = 0; t < 4; t++) {
            float4 v = acc[t];
            v.x += b4.x; v.y += b4.y; v.z += b4.z; v.w += b4.w;
            float ss = v.x * v.x + v.y * v.y + v.z * v.z + v.w * v.w;
            #pragma unroll
            for (int o = 16; o > 0; o >>= 1)
                ss += __shfl_xor_sync(0xffffffffu, ss, o);
            float inv_norm = 1.0f / fmaxf(sqrtf(ss), 1e-12f);
            int r = rbase + t;
            if (r < NN) {
                float4 o4;
                o4.x = fmaxf(v.x, 0.f) * inv_norm;
                o4.y = fmaxf(v.y, 0.f) * inv_norm;
                o4.z = fmaxf(v.z, 0.f) * inv_norm;
                o4.w = fmaxf(v.w, 0.f) * inv_norm;
                reinterpret_cast<float4*>(outp + (size_t)r * DD)[lane] = o4;
            }
        }
        __syncwarp();   // rows buffer reused next iteration (warp-private)
    }
}

// ---------------------------------------------------------------------------
// Launch sequence (all on the capture stream, no sync, no allocation)
// ---------------------------------------------------------------------------
extern "C" void kernel_launch(void* const* d_in, const int* in_sizes, int n_in,
                              void* d_out, int out_size) {
    const float* x   = (const float*)d_in[0];
    const void*  ei  = d_in[1];
    const float* W1l = (const float*)d_in[2];
    const float* b1l = (const float*)d_in[3];
    const float* W1r = (const float*)d_in[4];
    const float* W2l = (const float*)d_in[5];
    const float* b2l = (const float*)d_in[6];
    const float* W2r = (const float*)d_in[7];
    float* out = (float*)d_out;

    const int smem = (2 * DD * DD + 16 * 8 * DD) * (int)sizeof(float);  // 192 KB
    cudaFuncSetAttribute(sage_layer, cudaFuncAttributeMaxDynamicSharedMemorySize, smem);

    const int scatter_blocks = (EE * 32 + 255) / 256;

    // Probe edge_index dtype (int32 vs int64) once per launch sequence.
    detect_kernel<<<1, 1>>>((const int*)ei);

    // Layer 1
    zero_kernel<<<2048, 256>>>(1);
    scatter_kernel<<<scatter_blocks, 256>>>(x, ei, /*xin_is_gh=*/0, /*do_cnt=*/1);
    sage_layer<<<152, SAGE_THREADS, smem>>>(x, /*xin_is_gh=*/0, W1l, b1l, W1r,
                                            out, /*out_is_gh=*/1);

    // Layer 2 (cnt is identical, only re-zero agg)
    zero_kernel<<<2048, 256>>>(0);
    scatter_kernel<<<scatter_blocks, 256>>>(x, ei, /*xin_is_gh=*/1, /*do_cnt=*/0);
    sage_layer<<<152, SAGE_THREADS, smem>>>(x, /*xin_is_gh=*/1, W2l, b2l, W2r,
                                            out, /*out_is_gh=*/0);
}

// round 6
// speedup vs baseline: 2.4818x; 1.0047x over previous
#include <cuda_runtime.h>
#include <math.h>

#define NN 50000
#define EE 800000
#define DD 128
#define SAGE_THREADS 512          // 16 warps
#define ROWS_PER_ITER 64          // 16 warps x 4 rows

// Scratch (device globals: no allocation allowed in kernel_launch)
__device__ __align__(16) float g_agg[(size_t)NN * DD];
__device__ __align__(16) float g_cnt[NN];
__device__ __align__(16) float g_h[(size_t)NN * DD];
__device__ int g_ei_is64;

// ---------------------------------------------------------------------------
// Detect edge_index dtype. Values are in [0, 50000), so for a little-endian
// int64 buffer every odd 32-bit word is 0. For an int32 buffer, 16 sampled
// odd words all being zero is impossible in practice.
// ---------------------------------------------------------------------------
__global__ void detect_kernel(const int* __restrict__ ei32) {
    int all0 = 1;
    #pragma unroll
    for (int i = 0; i < 16; i++)
        if (ei32[2 * i + 1] != 0) all0 = 0;
    g_ei_is64 = all0;
}

// ---------------------------------------------------------------------------
// Zero the aggregation buffers. zero_cnt!=0 also zeroes the count buffer.
// ---------------------------------------------------------------------------
__global__ void zero_kernel(int zero_cnt) {
    int i = blockIdx.x * blockDim.x + threadIdx.x;
    int stride = gridDim.x * blockDim.x;
    float4 z = make_float4(0.f, 0.f, 0.f, 0.f);
    float4* agg4 = reinterpret_cast<float4*>(g_agg);
    for (int k = i; k < NN * DD / 4; k += stride) agg4[k] = z;
    if (zero_cnt) {
        float4* cnt4 = reinterpret_cast<float4*>(g_cnt);
        for (int k = i; k < NN / 4; k += stride) cnt4[k] = z;
    }
}

// ---------------------------------------------------------------------------
// Edge scatter: one warp per edge. Lane l handles 4 consecutive floats via
// a single vectorized red.global.add.v4.f32 (PTX ISA 8.1, sm_90+).
// ---------------------------------------------------------------------------
__global__ void scatter_kernel(const float* __restrict__ x_ext,
                               const void* __restrict__ ei_raw,
                               int xin_is_gh, int do_cnt) {
    const float* __restrict__ x = xin_is_gh ? g_h : x_ext;
    int gw = (blockIdx.x * blockDim.x + threadIdx.x) >> 5;
    int lane = threadIdx.x & 31;
    if (gw >= EE) return;

    int src, dst;
    if (g_ei_is64) {
        const long long* ei = (const long long*)ei_raw;
        src = (int)ei[gw];
        dst = (int)ei[EE + gw];
    } else {
        const int* ei = (const int*)ei_raw;
        src = ei[gw];
        dst = ei[EE + gw];
    }

    float4 v = reinterpret_cast<const float4*>(x + (size_t)src * DD)[lane];
    float* a = g_agg + (size_t)dst * DD + lane * 4;
    asm volatile("red.global.add.v4.f32 [%0], {%1, %2, %3, %4};"
                 :: "l"(a), "f"(v.x), "f"(v.y), "f"(v.z), "f"(v.w)
                 : "memory");
    if (do_cnt && lane == 0) atomicAdd(&g_cnt[dst], 1.0f);
}

// ---------------------------------------------------------------------------
// Fused SAGE layer:
//   mean = agg / max(cnt,1);  out = mean @ W_l + b_l + x @ W_r
//   out  = relu(out / max(||out||_2, 1e-12))
//
// 512 threads = 16 warps. Each iteration covers 64 rows. Warp g owns rows
// 4g..4g+3; lane c owns output columns 4c..4c+3 (float4). Weights are staged
// k-major in smem (contiguous 512B per warp LDS -> conflict-free). Row tiles
// are warp-private in smem (broadcast LDS). No block barriers in main loop;
// row norm is a warp-local butterfly reduction.
// ---------------------------------------------------------------------------
__global__ void __launch_bounds__(SAGE_THREADS, 1)
sage_layer(const float* __restrict__ xin_ext, int xin_is_gh,
           const float* __restrict__ Wl,
           const float* __restrict__ bl,
           const float* __restrict__ Wr,
           float* __restrict__ out_ext, int out_is_gh) {
    extern __shared__ float sh[];
    float* sWl = sh;                  // [128][128] k-major
    float* sWr = sWl + DD * DD;       // [128][128]
    float* srows = sWr + DD * DD;     // 16 warps x [8][128]: 4 mean rows, 4 x rows

    const float* __restrict__ xin = xin_is_gh ? g_h : xin_ext;
    float* __restrict__ outp = out_is_gh ? g_h : out_ext;

    int tid  = threadIdx.x;
    int warp = tid >> 5;
    int lane = tid & 31;

    // Stage weights (unpermuted, k-major)
    for (int idx = tid; idx < DD * DD; idx += SAGE_THREADS) {
        sWl[idx] = Wl[idx];
        sWr[idx] = Wr[idx];
    }
    float4 b4 = reinterpret_cast<const float4*>(bl)[lane];
    __syncthreads();

    float* mrow = srows + warp * 8 * DD;   // [4][128]
    float* xrow = mrow + 4 * DD;           // [4][128]

    for (int r0 = blockIdx.x * ROWS_PER_ITER; r0 < NN;
         r0 += gridDim.x * ROWS_PER_ITER) {
        int rbase = r0 + warp * 4;

        // Stage this warp's 4 rows (mean + x), float4 per lane (coalesced)
        #pragma unroll
        for (int t = 0; t < 4; t++) {
            int r = rbase + t;
            float4 a = make_float4(0.f, 0.f, 0.f, 0.f);
            float4 xv = a;
            if (r < NN) {
                float inv = 1.0f / fmaxf(g_cnt[r], 1.0f);
                a = reinterpret_cast<const float4*>(g_agg + (size_t)r * DD)[lane];
                a.x *= inv; a.y *= inv; a.z *= inv; a.w *= inv;
                xv = reinterpret_cast<const float4*>(xin + (size_t)r * DD)[lane];
            }
            reinterpret_cast<float4*>(mrow + t * DD)[lane] = a;
            reinterpret_cast<float4*>(xrow + t * DD)[lane] = xv;
        }
        __syncwarp();

        float4 acc[4];
        #pragma unroll
        for (int t = 0; t < 4; t++) acc[t] = make_float4(0.f, 0.f, 0.f, 0.f);

        #pragma unroll 2
        for (int k = 0; k < DD; k += 4) {
            float4 wl0 = *reinterpret_cast<const float4*>(sWl + (k + 0) * DD + 4 * lane);
            float4 wl1 = *reinterpret_cast<const float4*>(sWl + (k + 1) * DD + 4 * lane);
            float4 wl2 = *reinterpret_cast<const float4*>(sWl + (k + 2) * DD + 4 * lane);
            float4 wl3 = *reinterpret_cast<const float4*>(sWl + (k + 3) * DD + 4 * lane);
            float4 wr0 = *reinterpret_cast<const float4*>(sWr + (k + 0) * DD + 4 * lane);
            float4 wr1 = *reinterpret_cast<const float4*>(sWr + (k + 1) * DD + 4 * lane);
            float4 wr2 = *reinterpret_cast<const float4*>(sWr + (k + 2) * DD + 4 * lane);
            float4 wr3 = *reinterpret_cast<const float4*>(sWr + (k + 3) * DD + 4 * lane);
            #pragma unroll
            for (int t = 0; t < 4; t++) {
                float4 m = *reinterpret_cast<const float4*>(mrow + t * DD + k);
                float4 xv = *reinterpret_cast<const float4*>(xrow + t * DD + k);
                acc[t].x = fmaf(m.x, wl0.x, acc[t].x);
                acc[t].y = fmaf(m.x, wl0.y, acc[t].y);
                acc[t].z = fmaf(m.x, wl0.z, acc[t].z);
                acc[t].w = fmaf(m.x, wl0.w, acc[t].w);
                acc[t].x = fmaf(m.y, wl1.x, acc[t].x);
                acc[t].y = fmaf(m.y, wl1.y, acc[t].y);
                acc[t].z = fmaf(m.y, wl1.z, acc[t].z);
                acc[t].w = fmaf(m.y, wl1.w, acc[t].w);
                acc[t].x = fmaf(m.z, wl2.x, acc[t].x);
                acc[t].y = fmaf(m.z, wl2.y, acc[t].y);
                acc[t].z = fmaf(m.z, wl2.z, acc[t].z);
                acc[t].w = fmaf(m.z, wl2.w, acc[t].w);
                acc[t].x = fmaf(m.w, wl3.x, acc[t].x);
                acc[t].y = fmaf(m.w, wl3.y, acc[t].y);
                acc[t].z = fmaf(m.w, wl3.z, acc[t].z);
                acc[t].w = fmaf(m.w, wl3.w, acc[t].w);
                acc[t].x = fmaf(xv.x, wr0.x, acc[t].x);
                acc[t].y = fmaf(xv.x, wr0.y, acc[t].y);
                acc[t].z = fmaf(xv.x, wr0.z, acc[t].z);
                acc[t].w = fmaf(xv.x, wr0.w, acc[t].w);
                acc[t].x = fmaf(xv.y, wr1.x, acc[t].x);
                acc[t].y = fmaf(xv.y, wr1.y, acc[t].y);
                acc[t].z = fmaf(xv.y, wr1.z, acc[t].z);
                acc[t].w = fmaf(xv.y, wr1.w, acc[t].w);
                acc[t].x = fmaf(xv.z, wr2.x, acc[t].x);
                acc[t].y = fmaf(xv.z, wr2.y, acc[t].y);
                acc[t].z = fmaf(xv.z, wr2.z, acc[t].z);
                acc[t].w = fmaf(xv.z, wr2.w, acc[t].w);
                acc[t].x = fmaf(xv.w, wr3.x, acc[t].x);
                acc[t].y = fmaf(xv.w, wr3.y, acc[t].y);
                acc[t].z = fmaf(xv.w, wr3.z, acc[t].z);
                acc[t].w = fmaf(xv.w, wr3.w, acc[t].w);
            }
        }

        // Epilogue: bias, warp-local L2 norm per row, relu, store
        #pragma unroll
        for (int t = 0; t < 4; t++) {
            float4 v = acc[t];
            v.x += b4.x; v.y += b4.y; v.z += b4.z; v.w += b4.w;
            float ss = v.x * v.x + v.y * v.y + v.z * v.z + v.w * v.w;
            #pragma unroll
            for (int o = 16; o > 0; o >>= 1)
                ss += __shfl_xor_sync(0xffffffffu, ss, o);
            float inv_norm = 1.0f / fmaxf(sqrtf(ss), 1e-12f);
            int r = rbase + t;
            if (r < NN) {
                float4 o4;
                o4.x = fmaxf(v.x, 0.f) * inv_norm;
                o4.y = fmaxf(v.y, 0.f) * inv_norm;
                o4.z = fmaxf(v.z, 0.f) * inv_norm;
                o4.w = fmaxf(v.w, 0.f) * inv_norm;
                reinterpret_cast<float4*>(outp + (size_t)r * DD)[lane] = o4;
            }
        }
        __syncwarp();   // rows buffer reused next iteration (warp-private)
    }
}

// ---------------------------------------------------------------------------
// Launch sequence (all on the capture stream, no sync, no allocation)
// ---------------------------------------------------------------------------
extern "C" void kernel_launch(void* const* d_in, const int* in_sizes, int n_in,
                              void* d_out, int out_size) {
    const float* x   = (const float*)d_in[0];
    const void*  ei  = d_in[1];
    const float* W1l = (const float*)d_in[2];
    const float* b1l = (const float*)d_in[3];
    const float* W1r = (const float*)d_in[4];
    const float* W2l = (const float*)d_in[5];
    const float* b2l = (const float*)d_in[6];
    const float* W2r = (const float*)d_in[7];
    float* out = (float*)d_out;

    const int smem = (2 * DD * DD + 16 * 8 * DD) * (int)sizeof(float);  // 192 KB
    cudaFuncSetAttribute(sage_layer, cudaFuncAttributeMaxDynamicSharedMemorySize, smem);

    const int scatter_blocks = (EE * 32 + 255) / 256;

    // Probe edge_index dtype (int32 vs int64) once per launch sequence.
    detect_kernel<<<1, 1>>>((const int*)ei);

    // Layer 1
    zero_kernel<<<2048, 256>>>(1);
    scatter_kernel<<<scatter_blocks, 256>>>(x, ei, /*xin_is_gh=*/0, /*do_cnt=*/1);
    sage_layer<<<152, SAGE_THREADS, smem>>>(x, /*xin_is_gh=*/0, W1l, b1l, W1r,
                                            out, /*out_is_gh=*/1);

    // Layer 2 (cnt is identical, only re-zero agg)
    zero_kernel<<<2048, 256>>>(0);
    scatter_kernel<<<scatter_blocks, 256>>>(x, ei, /*xin_is_gh=*/1, /*do_cnt=*/0);
    sage_layer<<<152, SAGE_THREADS, smem>>>(x, /*xin_is_gh=*/1, W2l, b2l, W2r,
                                            out, /*out_is_gh=*/0);
}